// round 1
// baseline (speedup 1.0000x reference)
#include <cuda_runtime.h>
#include <math.h>

#define BB  256      // batch
#define HH  256      // hidden
#define NLY 6        // layers
#define SS  128      // steps
#define K0  128      // CIN*WIN
#define G3  768      // 3*H

struct Ptrs {
  const float *x, *Wih0, *Wih, *Whh, *bih, *bhh, *h0;
  const float *aW1, *aW2, *aW3, *aW4;
  const float *sdW1,*sdb1,*sdW2,*sdb2,*sdW3,*sdb3,*sdW4,*sdb4;
  const float *odW1,*odb1,*odW2,*odb2,*odW3,*odb3,*odW4,*odb4;
  float* out;
};

// scratch (device globals -- no allocation allowed)
__device__ __align__(16) float g_h[2][NLY][BB][HH];     // recurrent h, double-buffered by wavefront parity
__device__ __align__(16) float g_hpre[NLY][BB][HH];     // GRU output (pre-attn)
__device__ __align__(16) float g_sh[NLY][BB][HH];       // sorted rows
__device__ __align__(16) float g_Gi[NLY][BB][G3];
__device__ __align__(16) float g_Gh[NLY][BB][G3];
__device__ __align__(16) float g_A1[NLY][BB][512];
__device__ __align__(16) float g_A2[NLY][BB][512];
__device__ __align__(16) float g_A3[NLY][BB][512];
__device__ __align__(16) float g_W2p[NLY][128][128];    // shuffle-permuted W2
__device__ __align__(16) float g_W3p[NLY][128][128];

#define TM_ 64
#define TN_ 64
#define TK_ 16

#define YSEQ_OFF 8388608ul           // 256*128*256
#define YONE_OFF 9437184ul           // + 256*1024*4

// ---------------------------------------------------------------------------
// Tiled GEMM core: out_tile[64 x 64] = A[64 x K] * Bw[64 x K]^T
// A row base (m0 applied) with stride lda; optional column gather (SortAttn
// shuffle): colA = (k>>5)*128 + gbase + (k&31).  Bw row base (n0 applied),
// row-major with stride ldb (= K).
// ---------------------------------------------------------------------------
__device__ __forceinline__ void gemm_tile(
    const float* __restrict__ A, int lda,
    const float* __restrict__ Bw, int ldb,
    int K, int gather, int gbase,
    float acc[4][4], float* As, float* Bs)
{
  const int t  = threadIdx.x;
  const int lr = t >> 2;             // 0..63 (tile row for loading)
  const int lc = (t & 3) << 2;       // 0,4,8,12 (k offset, float4)
  const int tx = t & 15, ty = t >> 4;
  for (int k0 = 0; k0 < K; k0 += TK_) {
    int c = k0 + lc;
    int colA = gather ? (((c >> 5) << 7) + gbase + (c & 31)) : c;
    float4 av = *reinterpret_cast<const float4*>(A + (size_t)lr * lda + colA);
    As[(lc+0)*TM_ + lr] = av.x; As[(lc+1)*TM_ + lr] = av.y;
    As[(lc+2)*TM_ + lr] = av.z; As[(lc+3)*TM_ + lr] = av.w;
    float4 bv = *reinterpret_cast<const float4*>(Bw + (size_t)lr * ldb + c);
    Bs[(lc+0)*TN_ + lr] = bv.x; Bs[(lc+1)*TN_ + lr] = bv.y;
    Bs[(lc+2)*TN_ + lr] = bv.z; Bs[(lc+3)*TN_ + lr] = bv.w;
    __syncthreads();
#pragma unroll
    for (int kk = 0; kk < TK_; kk++) {
      float4 a4 = *reinterpret_cast<const float4*>(As + kk*TM_ + (ty<<2));
      float4 b4 = *reinterpret_cast<const float4*>(Bs + kk*TN_ + (tx<<2));
      float av_[4] = {a4.x, a4.y, a4.z, a4.w};
      float bv_[4] = {b4.x, b4.y, b4.z, b4.w};
#pragma unroll
      for (int i = 0; i < 4; i++)
#pragma unroll
        for (int j = 0; j < 4; j++)
          acc[i][j] += av_[i] * bv_[j];
    }
    __syncthreads();
  }
}

// ---------------------------------------------------------------------------
// prep: permute aW2/aW3 so the shuffled-activation GEMM reads contiguously.
// W2p[l][j][rr*32+q] = W2[l][j][4*q+rr]
// ---------------------------------------------------------------------------
__global__ void prep_kernel(Ptrs P) {
  int i = blockIdx.x * blockDim.x + threadIdx.x;
  const int total = NLY * 128 * 128;
  if (i < total) {
    int l = i >> 14; int r = i & 16383; int j = r >> 7; int m = r & 127;
    int src = l * 16384 + j * 128 + ((m & 31) << 2) + (m >> 5);
    g_W2p[l][j][m] = P.aW2[src];
    g_W3p[l][j][m] = P.aW3[src];
  }
}

// ---------------------------------------------------------------------------
// Stage 1: Gi = inp @ Wih^T ; Gh = h_prev @ Whh^T   (biases added in gates)
// grid (48, nActiveLayers, 2)
// ---------------------------------------------------------------------------
__global__ void gru_gemm_kernel(Ptrs P, int w, int lmin, int pp) {
  __shared__ float As[TK_*TM_], Bs[TK_*TN_];
  int l = lmin + blockIdx.y, t = w - l;
  int m0 = (blockIdx.x & 3) << 6;
  int n0 = (blockIdx.x >> 2) << 6;
  const float *A, *W; int lda, K; float* out;
  if (blockIdx.z == 0) {
    if (l == 0) { A = P.x + (size_t)t * K0 + (size_t)m0 * 16384; lda = 16384; K = K0;
                  W = P.Wih0 + (size_t)n0 * K0; }
    else        { A = &g_h[pp][l-1][m0][0]; lda = HH; K = HH;
                  W = P.Wih + ((size_t)(l-1) * G3 + n0) * HH; }
    out = &g_Gi[l][0][0];
  } else {
    if (t == 0) { A = P.h0 + l * HH; lda = 0; }
    else        { A = &g_h[pp][l][m0][0]; lda = HH; }
    K = HH; W = P.Whh + ((size_t)l * G3 + n0) * HH;
    out = &g_Gh[l][0][0];
  }
  float acc[4][4] = {};
  gemm_tile(A, lda, W, K, K, 0, 0, acc, As, Bs);
  int tx = threadIdx.x & 15, ty = threadIdx.x >> 4;
#pragma unroll
  for (int i = 0; i < 4; i++) {
    float4 v = make_float4(acc[i][0], acc[i][1], acc[i][2], acc[i][3]);
    *reinterpret_cast<float4*>(out + (size_t)(m0 + (ty<<2) + i) * G3 + n0 + (tx<<2)) = v;
  }
}

// ---------------------------------------------------------------------------
// Stage 2: GRU gates -> g_hpre
// ---------------------------------------------------------------------------
__global__ void gates_kernel(Ptrs P, int w, int lmin, int pp) {
  int l = lmin + blockIdx.y, t = w - l;
  int idx = blockIdx.x * 256 + threadIdx.x;
  int b = idx >> 8, j = idx & 255;
  const float* bi = P.bih + l * G3;
  const float* bh = P.bhh + l * G3;
  float gi0 = g_Gi[l][b][j] + bi[j];
  float gi1 = g_Gi[l][b][j+256] + bi[j+256];
  float gi2 = g_Gi[l][b][j+512] + bi[j+512];
  float gh0 = g_Gh[l][b][j] + bh[j];
  float gh1 = g_Gh[l][b][j+256] + bh[j+256];
  float gh2 = g_Gh[l][b][j+512] + bh[j+512];
  float r = 1.f / (1.f + expf(-(gi0 + gh0)));
  float z = 1.f / (1.f + expf(-(gi1 + gh1)));
  float n = tanhf(gi2 + r * gh2);
  float hp = (t == 0) ? P.h0[l * HH + j] : g_h[pp][l][b][j];
  g_hpre[l][b][j] = (1.f - z) * n + z * hp;
}

// ---------------------------------------------------------------------------
// Stage 3: per-row bitonic sort (ascending) of hpre -> g_sh
// ---------------------------------------------------------------------------
__global__ void sort_kernel(int lmin) {
  int l = lmin + blockIdx.y, b = blockIdx.x;
  __shared__ float v[256];
  int tid = threadIdx.x;
  v[tid] = g_hpre[l][b][tid];
  __syncthreads();
  for (int k = 2; k <= 256; k <<= 1) {
    for (int j = k >> 1; j > 0; j >>= 1) {
      int ixj = tid ^ j;
      if (ixj > tid) {
        float a = v[tid], c = v[ixj];
        bool up = ((tid & k) == 0);
        if ((a > c) == up) { v[tid] = c; v[ixj] = a; }
      }
      __syncthreads();
    }
  }
  g_sh[l][b][tid] = v[tid];
}

// ---------------------------------------------------------------------------
// Stage 4: A1[b, c] = (c<256 ? hpre : sorted)[b,:] . W1[c%256,:]
// ---------------------------------------------------------------------------
__global__ void a1_kernel(Ptrs P, int lmin) {
  __shared__ float As[TK_*TM_], Bs[TK_*TN_];
  int l = lmin + blockIdx.y;
  int m0 = (blockIdx.x & 3) << 6;
  int n0 = (blockIdx.x >> 2) << 6;            // 0..448
  const float* A = (n0 < 256) ? &g_hpre[l][m0][0] : &g_sh[l][m0][0];
  const float* W = P.aW1 + ((size_t)l * 256 + (n0 & 255)) * 256;
  float acc[4][4] = {};
  gemm_tile(A, HH, W, 256, 256, 0, 0, acc, As, Bs);
  int tx = threadIdx.x & 15, ty = threadIdx.x >> 4;
  float* out = &g_A1[l][0][0];
#pragma unroll
  for (int i = 0; i < 4; i++) {
    float4 v = make_float4(acc[i][0], acc[i][1], acc[i][2], acc[i][3]);
    *reinterpret_cast<float4*>(out + (size_t)(m0 + (ty<<2) + i) * 512 + n0 + (tx<<2)) = v;
  }
}

// ---------------------------------------------------------------------------
// Stage 5/6: A2 = shuffle(A1) @ W2p^T ; A3 = relu(shuffle(A2) @ W3p^T)
// shuffle folded: src col(k) = (k>>5)*128 + group*32 + (k&31), weights pre-permuted
// ---------------------------------------------------------------------------
__global__ void a23_kernel(Ptrs P, int lmin, int which) {
  __shared__ float As[TK_*TM_], Bs[TK_*TN_];
  int l = lmin + blockIdx.y;
  int m0 = (blockIdx.x & 3) << 6;
  int f0 = (blockIdx.x >> 2) << 6;
  int grp = f0 >> 7, j0 = f0 & 127;
  const float* A = (which == 2) ? &g_A1[l][m0][0] : &g_A2[l][m0][0];
  const float* W = (which == 2) ? &g_W2p[l][j0][0] : &g_W3p[l][j0][0];
  float* out     = (which == 2) ? &g_A2[l][0][0]  : &g_A3[l][0][0];
  float acc[4][4] = {};
  gemm_tile(A, 512, W, 128, 128, 1, grp * 32, acc, As, Bs);
  int tx = threadIdx.x & 15, ty = threadIdx.x >> 4;
#pragma unroll
  for (int i = 0; i < 4; i++) {
    float4 v = make_float4(acc[i][0], acc[i][1], acc[i][2], acc[i][3]);
    if (which == 3) {
      v.x = fmaxf(v.x, 0.f); v.y = fmaxf(v.y, 0.f);
      v.z = fmaxf(v.z, 0.f); v.w = fmaxf(v.w, 0.f);
    }
    *reinterpret_cast<float4*>(out + (size_t)(m0 + (ty<<2) + i) * 512 + f0 + (tx<<2)) = v;
  }
}

// ---------------------------------------------------------------------------
// Stage 7: a4 = A3flat @ W4^T ; h_out = hpre * sigmoid(a4); store h + enc
// ---------------------------------------------------------------------------
__global__ void a4_kernel(Ptrs P, int w, int lmin, int p) {
  __shared__ float As[TK_*TM_], Bs[TK_*TN_];
  int l = lmin + blockIdx.y, t = w - l;
  int m0 = (blockIdx.x & 3) << 6;
  int n0 = (blockIdx.x >> 2) << 6;
  const float* A = &g_A3[l][m0][0];
  const float* W = P.aW4 + ((size_t)l * 256 + n0) * 512;
  float acc[4][4] = {};
  gemm_tile(A, 512, W, 512, 512, 0, 0, acc, As, Bs);
  int tx = threadIdx.x & 15, ty = threadIdx.x >> 4;
#pragma unroll
  for (int i = 0; i < 4; i++) {
    int m = m0 + (ty<<2) + i;
#pragma unroll
    for (int j = 0; j < 4; j++) {
      int n = n0 + (tx<<2) + j;
      float sg = 1.f / (1.f + expf(-acc[i][j]));
      float hv = g_hpre[l][m][n] * sg;
      g_h[p][l][m][n] = hv;
      if (l == NLY - 1)
        P.out[(size_t)m * 32768 + (size_t)t * 256 + n] = hv;   // enc[b,t,j]
    }
  }
}

// ---------------------------------------------------------------------------
// SeqDecoder: one thread per (b,s)
// ---------------------------------------------------------------------------
__global__ void seqdec_kernel(Ptrs P) {
  int idx = blockIdx.x * blockDim.x + threadIdx.x;
  int b = idx >> 7, s = idx & 127;
  const float* e = P.out + (size_t)b * 32768 + (size_t)s * 256;
  float a1[8][4], a2[8][4], a3[8][4];
#pragma unroll
  for (int g = 0; g < 8; g++)
#pragma unroll
    for (int o = 0; o < 4; o++) {
      float sum = P.sdb1[o];
#pragma unroll
      for (int m = 0; m < 32; m++) sum += e[g*32+m] * P.sdW1[o*32+m];
      a1[g][o] = sum;
    }
#pragma unroll
  for (int i = 0; i < 8; i++)
#pragma unroll
    for (int o = 0; o < 4; o++) {
      float sum = P.sdb2[o];
#pragma unroll
      for (int j = 0; j < 4; j++) {
        int f = i*4 + j;
        sum += a1[f & 7][f >> 3] * P.sdW2[o*4+j];
      }
      a2[i][o] = sum;
    }
#pragma unroll
  for (int i = 0; i < 8; i++)
#pragma unroll
    for (int o = 0; o < 4; o++) {
      float sum = P.sdb3[o];
#pragma unroll
      for (int j = 0; j < 4; j++) {
        int f = i*4 + j;
        sum += a2[f & 7][f >> 3] * P.sdW3[o*4+j];
      }
      a3[i][o] = sum;
    }
#pragma unroll
  for (int o = 0; o < 4; o++)
#pragma unroll
    for (int wv = 0; wv < 8; wv++) {
      float sum = P.sdb4[wv];
#pragma unroll
      for (int g = 0; g < 8; g++) {
        int f = o*8 + g;
        sum += a3[f >> 2][f & 3] * P.sdW4[wv*8+g];
      }
      P.out[YSEQ_OFF + (size_t)b * 4096 + (size_t)(s*8 + wv) * 4 + o] = sum;
    }
}

// ---------------------------------------------------------------------------
// OneDecoder: block per b; threads 0..9 handle s = 118..127, then mean
// ---------------------------------------------------------------------------
__global__ void onedec_kernel(Ptrs P) {
  int b = blockIdx.x;
  __shared__ float acc[10][4];
  int tid = threadIdx.x;
  if (tid < 10) {
    int s = 118 + tid;
    const float* e = P.out + (size_t)b * 32768 + (size_t)s * 256;
    float o1[8][4], o2[8][4], o3[8][4];
#pragma unroll
    for (int g = 0; g < 8; g++)
#pragma unroll
      for (int o = 0; o < 4; o++) {
        float sum = P.odb1[o];
#pragma unroll
        for (int m = 0; m < 32; m++) sum += e[g*32+m] * P.odW1[o*32+m];
        o1[g][o] = sum;
      }
#pragma unroll
    for (int i = 0; i < 8; i++)
#pragma unroll
      for (int o = 0; o < 4; o++) {
        float sum = P.odb2[o];
#pragma unroll
        for (int j = 0; j < 4; j++) {
          int f = i*4 + j;
          sum += o1[f & 7][f >> 3] * P.odW2[o*4+j];
        }
        o2[i][o] = sum;
      }
#pragma unroll
    for (int i = 0; i < 8; i++)
#pragma unroll
      for (int o = 0; o < 4; o++) {
        float sum = P.odb3[o];
#pragma unroll
        for (int j = 0; j < 4; j++) {
          int f = i*4 + j;
          sum += o2[f & 7][f >> 3] * P.odW3[o*4+j];
        }
        o3[i][o] = fmaxf(sum, 0.f);
      }
#pragma unroll
    for (int c = 0; c < 4; c++) {
      float sum = P.odb4[c];
#pragma unroll
      for (int f = 0; f < 32; f++) sum += o3[f >> 2][f & 3] * P.odW4[c*32+f];
      acc[tid][c] = 1.f / (1.f + expf(-sum));
    }
  }
  __syncthreads();
  if (tid < 4) {
    float s = 0.f;
#pragma unroll
    for (int i = 0; i < 10; i++) s += acc[i][tid];
    P.out[YONE_OFF + (size_t)b * 4 + tid] = s * 0.1f;
  }
}

// ---------------------------------------------------------------------------
extern "C" void kernel_launch(void* const* d_in, const int* in_sizes, int n_in,
                              void* d_out, int out_size) {
  (void)in_sizes; (void)n_in; (void)out_size;
  Ptrs P;
  P.x    = (const float*)d_in[0];
  P.Wih0 = (const float*)d_in[1];
  P.Wih  = (const float*)d_in[2];
  P.Whh  = (const float*)d_in[3];
  P.bih  = (const float*)d_in[4];
  P.bhh  = (const float*)d_in[5];
  P.h0   = (const float*)d_in[6];
  P.aW1  = (const float*)d_in[7];
  P.aW2  = (const float*)d_in[8];
  P.aW3  = (const float*)d_in[9];
  P.aW4  = (const float*)d_in[10];
  P.sdW1 = (const float*)d_in[11];
  P.sdb1 = (const float*)d_in[12];
  P.sdW2 = (const float*)d_in[13];
  P.sdb2 = (const float*)d_in[14];
  P.sdW3 = (const float*)d_in[15];
  P.sdb3 = (const float*)d_in[16];
  P.sdW4 = (const float*)d_in[17];
  P.sdb4 = (const float*)d_in[18];
  P.odW1 = (const float*)d_in[19];
  P.odb1 = (const float*)d_in[20];
  P.odW2 = (const float*)d_in[21];
  P.odb2 = (const float*)d_in[22];
  P.odW3 = (const float*)d_in[23];
  P.odb3 = (const float*)d_in[24];
  P.odW4 = (const float*)d_in[25];
  P.odb4 = (const float*)d_in[26];
  P.out  = (float*)d_out;

  prep_kernel<<<384, 256>>>(P);

  for (int w = 0; w < SS + NLY - 1; w++) {
    int lmin = w - (SS - 1); if (lmin < 0) lmin = 0;
    int lmax = (w < NLY - 1) ? w : NLY - 1;
    int nA = lmax - lmin + 1;
    int pp = (w + 1) & 1;   // parity of wavefront w-1
    int p  = w & 1;
    gru_gemm_kernel<<<dim3(48, nA, 2), 256>>>(P, w, lmin, pp);
    gates_kernel<<<dim3(256, nA), 256>>>(P, w, lmin, pp);
    sort_kernel<<<dim3(256, nA), 256>>>(lmin);
    a1_kernel<<<dim3(32, nA), 256>>>(P, lmin);
    a23_kernel<<<dim3(32, nA), 256>>>(P, lmin, 2);
    a23_kernel<<<dim3(32, nA), 256>>>(P, lmin, 3);
    a4_kernel<<<dim3(16, nA), 256>>>(P, w, lmin, p);
  }

  seqdec_kernel<<<128, 256>>>(P);
  onedec_kernel<<<256, 32>>>(P);
}